// round 5
// baseline (speedup 1.0000x reference)
#include <cuda_runtime.h>
#include <cuda_fp16.h>
#include <math.h>
#include <stdint.h>

// ---------------------------------------------------------------------------
// Problem constants
#define BN_   256   // batch
#define TN_   256   // time steps
#define DN_   300   // input dim
#define HN_   512   // hidden
#define XPAD  320   // x padded to 320 (5 chunks of 64)
#define KPAD  832   // 320 + 512
#define NCHUNK 13   // 832 / 64
#define FOURH 2048

// ---------------------------------------------------------------------------
// Scratch (device globals) — inputs pre-split into fp16 hi/lo arrays
__device__ __half g_xhi[2ll * BN_ * TN_ * XPAD];
__device__ __half g_xlo[2ll * BN_ * TN_ * XPAD];
__device__ __half g_whi[4ll * FOURH * KPAD];
__device__ __half g_wlo[4ll * FOURH * KPAD];
__device__ float  g_bp [4 * FOURH];                 // permuted bias
__device__ __half g_hhi[2ll * 4 * BN_ * HN_];       // double-buffered h hi
__device__ __half g_hlo[2ll * 4 * BN_ * HN_];       // double-buffered h lo
__device__ float  g_c  [4][BN_][HN_];               // cell state
__device__ float  g_x  [BN_ * FOURH];               // concat c -> MLP input
__device__ float  g_m1[BN_ * 1024];
__device__ float  g_m2[BN_ * 1024];
__device__ float  g_m3[BN_ * 1024];

__device__ __forceinline__ float sigmoidf_(float v) { return 1.0f / (1.0f + expf(-v)); }

__device__ __forceinline__ uint32_t smem_u32(const void* p) {
    uint32_t a;
    asm("{ .reg .u64 t; cvta.to.shared.u64 t, %1; cvt.u32.u64 %0, t; }" : "=r"(a) : "l"(p));
    return a;
}
__device__ __forceinline__ void cp16(uint32_t dst, const void* src) {
    asm volatile("cp.async.cg.shared.global [%0], [%1], 16;" :: "r"(dst), "l"(src));
}
#define CP_COMMIT() asm volatile("cp.async.commit_group;" ::: "memory")
#define CP_WAIT(N)  asm volatile("cp.async.wait_group %0;" :: "n"(N) : "memory")

#define LDSM_X4(r0, r1, r2, r3, addr)                                         \
    asm volatile("ldmatrix.sync.aligned.m8n8.x4.shared.b16 {%0,%1,%2,%3}, [%4];" \
        : "=r"(r0), "=r"(r1), "=r"(r2), "=r"(r3) : "r"(addr))

// f32-accumulate HMMA (main product)
#define MMA16816(d, a, b)                                                     \
    asm volatile("mma.sync.aligned.m16n8k16.row.col.f32.f16.f16.f32 "         \
        "{%0,%1,%2,%3}, {%4,%5,%6,%7}, {%8,%9}, {%0,%1,%2,%3};"               \
        : "+f"((d)[0]), "+f"((d)[1]), "+f"((d)[2]), "+f"((d)[3])              \
        : "r"((a)[0]), "r"((a)[1]), "r"((a)[2]), "r"((a)[3]),                 \
          "r"((b)[0]), "r"((b)[1]))

// f16-accumulate HMMA (correction products; d = 2x f16x2 regs)
#define MMA16816H(d, a, b)                                                    \
    asm volatile("mma.sync.aligned.m16n8k16.row.col.f16.f16.f16.f16 "         \
        "{%0,%1}, {%2,%3,%4,%5}, {%6,%7}, {%0,%1};"                           \
        : "+r"((d)[0]), "+r"((d)[1])                                          \
        : "r"((a)[0]), "r"((a)[1]), "r"((a)[2]), "r"((a)[3]),                 \
          "r"((b)[0]), "r"((b)[1]))

// ---------------------------------------------------------------------------
// Fused one-shot preprocessing (single launch so ncu -s 5 lands on lstm_step)
struct WPtrs { const float* wx[4]; const float* wh[4]; const float* bias[4]; };

#define NX_ (2ll * BN_ * TN_ * XPAD)      // 41,943,040
#define NW_ (4ll * FOURH * KPAD)          //  6,815,744
#define NH_ (2ll * 4 * BN_ * HN_)         //  1,048,576
#define NC_ (4ll * BN_ * HN_)             //    524,288
#define NB_ (4ll * FOURH)                 //      8,192
#define NTOT_ (NX_ + NW_ + NH_ + NC_ + NB_)

__global__ void preproc_all(const float* __restrict__ prem, const float* __restrict__ hyp,
                            WPtrs wp) {
    long long i = (long long)blockIdx.x * blockDim.x + threadIdx.x;
    if (i < NX_) {                                   // x -> hi/lo split, padded
        int k = (int)(i % XPAD);
        long long r = i / XPAD;
        int t = (int)(r % TN_); r /= TN_;
        int b = (int)(r % BN_);
        int inp = (int)(r / BN_);
        float v = 0.0f;
        if (k < DN_) {
            const float* src = inp ? hyp : prem;
            v = src[((long long)b * TN_ + t) * DN_ + k];
        }
        __half h = __float2half(v);
        g_xhi[i] = h;
        g_xlo[i] = __float2half(v - __half2float(h));
        return;
    }
    i -= NX_;
    if (i < NW_) {                                   // W -> permuted/transposed hi/lo
        int kp = (int)(i % KPAD);
        long long r = i / KPAD;
        int c   = (int)(r % FOURH);
        int seq = (int)(r / FOURH);
        int oc  = (c & 3) * HN_ + (c >> 2);          // gate-interleaved col' = u*4+g
        float v = 0.0f;
        if (kp < DN_)        v = wp.wx[seq][(long long)kp * FOURH + oc];
        else if (kp >= XPAD) v = wp.wh[seq][(long long)(kp - XPAD) * FOURH + oc];
        __half h = __float2half(v);
        g_whi[i] = h;
        g_wlo[i] = __float2half(v - __half2float(h));
        return;
    }
    i -= NW_;
    if (i < NH_) {                                   // zero h buffers
        g_hhi[i] = __float2half(0.f);
        g_hlo[i] = __float2half(0.f);
        return;
    }
    i -= NH_;
    if (i < NC_) {                                   // zero c
        (&g_c[0][0][0])[i] = 0.0f;
        return;
    }
    i -= NC_;
    if (i < NB_) {                                   // permuted bias
        int c = (int)(i & (FOURH - 1));
        int seq = (int)(i >> 11);
        g_bp[i] = wp.bias[seq][(c & 3) * HN_ + (c >> 2)];
    }
}

// ---------------------------------------------------------------------------
// Fused LSTM step via mma.sync, fp16 hi/lo split. Main product f32-acc,
// correction products f16-acc (possible 2x rate path).
// Grid (16 n-tiles, 2 m-tiles, 4 seqs), 256 threads (8 warps: 2m x 4n).
#define ST_BYTES 65536
#define OFF_AL   16384
#define OFF_BH   32768
#define OFF_BL   49152
#define OFF_BIAS 131072
#define SMEM_TOTAL_STEP 131584

__global__ __launch_bounds__(256) void lstm_step_mma(const int* __restrict__ plen,
                                                     const int* __restrict__ hlen,
                                                     int s) {
    extern __shared__ char smem[];
    const uint32_t sbase = smem_u32(smem);
    const int tid  = threadIdx.x;
    const int lane = tid & 31;
    const int wid  = tid >> 5;
    const int warp_m = wid >> 2;       // 0..1
    const int warp_n = wid & 3;        // 0..3

    const int seq = blockIdx.z;
    const int rev = seq & 1;
    const int t   = rev ? (TN_ - 1 - s) : s;
    const int inp = seq >> 1;
    const int b0  = blockIdx.y * 128;
    const int n0  = blockIdx.x * 128;
    const int cur = s & 1;

    if (tid < 128)
        *(float*)(smem + OFF_BIAS + tid * 4) = g_bp[seq * FOURH + n0 + tid];

    const long hin_base  = ((long)cur * 4 + seq) * (BN_ * HN_);
    const long hout_base = ((long)(cur ^ 1) * 4 + seq) * (BN_ * HN_);

    // ---- chunk loader (cp.async) -----------------------------------------
    auto load_chunk = [&](int k, int p) {
        const uint32_t st = sbase + (p ? ST_BYTES : 0);
        const bool isx = (k < 5);
        const int k0 = k * 64;
        #pragma unroll
        for (int j = 0; j < 4; j++) {           // A: hi + lo
            int idx = tid + 256 * j;
            int row = idx >> 3;
            int seg = idx & 7;
            int kk  = k0 + seg * 8;
            long base;
            if (isx) base = ((long)(inp * BN_ + b0 + row) * TN_ + t) * XPAD + kk;
            else     base = hin_base + (long)(b0 + row) * HN_ + (kk - XPAD);
            uint32_t dst = st + ((row * 8 + (seg ^ (row & 7))) << 4);
            cp16(dst,          isx ? (const void*)(g_xhi + base) : (const void*)(g_hhi + base));
            cp16(dst + OFF_AL, isx ? (const void*)(g_xlo + base) : (const void*)(g_hlo + base));
        }
        #pragma unroll
        for (int j = 0; j < 4; j++) {           // B: hi + lo
            int idx = tid + 256 * j;
            int row = idx >> 3;
            int seg = idx & 7;
            int kk  = k0 + seg * 8;
            long base = ((long)seq * FOURH + n0 + row) * KPAD + kk;
            uint32_t dst = st + OFF_BH + ((row * 8 + (seg ^ (row & 7))) << 4);
            cp16(dst,         g_whi + base);
            cp16(dst + 16384, g_wlo + base);
        }
        CP_COMMIT();
    };

    // accumulators: main f32 [mi][ni][4], corrections f16x2 [mi][ni][2]
    float acc[4][4][4];
    uint32_t acch[4][4][2];
    #pragma unroll
    for (int mi = 0; mi < 4; mi++)
        #pragma unroll
        for (int ni = 0; ni < 4; ni++) {
            #pragma unroll
            for (int q = 0; q < 4; q++) acc[mi][ni][q] = 0.0f;
            acch[mi][ni][0] = 0u; acch[mi][ni][1] = 0u;
        }

    // per-lane ldmatrix row invariants
    int arowb[4], arowx[4];
    #pragma unroll
    for (int mi = 0; mi < 4; mi++) {
        int r = warp_m * 64 + mi * 16 + (lane & 15);
        arowb[mi] = r * 128;
        arowx[mi] = r & 7;
    }
    int brow[2], browx[2];
    #pragma unroll
    for (int np = 0; np < 2; np++) {
        int n = warp_n * 32 + np * 16 + ((lane >> 4) << 3) + (lane & 7);
        brow[np]  = n * 128;
        browx[np] = n & 7;
    }
    const int asel = lane >> 4;          // 0/1 -> k or k+8 half for A
    const int bsel = (lane >> 3) & 1;    // 0/1 -> k or k+8 half for B

    load_chunk(0, 0);

    for (int k = 0; k < NCHUNK; k++) {
        const int p = k & 1;
        if (k + 1 < NCHUNK) load_chunk(k + 1, p ^ 1);
        if (k + 1 < NCHUNK) CP_WAIT(1); else CP_WAIT(0);
        __syncthreads();

        const uint32_t st = sbase + (p ? ST_BYTES : 0);
        #pragma unroll
        for (int kk = 0; kk < 4; kk++) {
            uint32_t ah[4][4], al[4][4];
            #pragma unroll
            for (int mi = 0; mi < 4; mi++) {
                int seg = 2 * kk + asel;
                uint32_t off = arowb[mi] + ((seg ^ arowx[mi]) << 4);
                LDSM_X4(ah[mi][0], ah[mi][1], ah[mi][2], ah[mi][3], st + off);
                LDSM_X4(al[mi][0], al[mi][1], al[mi][2], al[mi][3], st + OFF_AL + off);
            }
            uint32_t bh[2][4], bl[2][4];
            #pragma unroll
            for (int np = 0; np < 2; np++) {
                int seg = 2 * kk + bsel;
                uint32_t off = brow[np] + ((seg ^ browx[np]) << 4);
                LDSM_X4(bh[np][0], bh[np][1], bh[np][2], bh[np][3], st + OFF_BH + off);
                LDSM_X4(bl[np][0], bl[np][1], bl[np][2], bl[np][3], st + OFF_BL + off);
            }
            #pragma unroll
            for (int mi = 0; mi < 4; mi++)
                #pragma unroll
                for (int np = 0; np < 2; np++)
                    #pragma unroll
                    for (int h = 0; h < 2; h++) {
                        int ni = np * 2 + h;
                        uint32_t bhf[2] = { bh[np][2 * h], bh[np][2 * h + 1] };
                        uint32_t blf[2] = { bl[np][2 * h], bl[np][2 * h + 1] };
                        MMA16816 (acc[mi][ni],  ah[mi], bhf);   // main, f32 acc
                        MMA16816H(acch[mi][ni], ah[mi], blf);   // corr, f16 acc
                        MMA16816H(acch[mi][ni], al[mi], bhf);   // corr, f16 acc
                    }
        }
        __syncthreads();
    }

    // ---- epilogue: merge corrections, gates + masked state update ---------
    const int* __restrict__ len = (seq < 2) ? plen : hlen;
    const float* bias_s = (const float*)(smem + OFF_BIAS);
    const bool amain = ((lane & 1) == 0);

    #pragma unroll
    for (int mi = 0; mi < 4; mi++) {
        #pragma unroll
        for (int ni = 0; ni < 4; ni++) {
            float2 c01 = __half22float2(*(__half2*)&acch[mi][ni][0]);
            float2 c23 = __half22float2(*(__half2*)&acch[mi][ni][1]);
            int col_local = warp_n * 32 + ni * 8 + 2 * (lane & 3);
            float v0 = acc[mi][ni][0] + c01.x + bias_s[col_local];
            float v1 = acc[mi][ni][1] + c01.y + bias_s[col_local + 1];
            float v2 = acc[mi][ni][2] + c23.x + bias_s[col_local];
            float v3 = acc[mi][ni][3] + c23.y + bias_s[col_local + 1];
            float p0 = __shfl_xor_sync(0xffffffffu, v0, 1);
            float p1 = __shfl_xor_sync(0xffffffffu, v1, 1);
            float p2 = __shfl_xor_sync(0xffffffffu, v2, 1);
            float p3 = __shfl_xor_sync(0xffffffffu, v3, 1);
            if (amain) {
                int u = (n0 + col_local) >> 2;
                #pragma unroll
                for (int rh = 0; rh < 2; rh++) {
                    int b = b0 + warp_m * 64 + mi * 16 + (lane >> 2) + rh * 8;
                    float iv = rh ? v2 : v0;
                    float jv = rh ? v3 : v1;
                    float fv = rh ? p2 : p0;
                    float ov = rh ? p3 : p1;
                    bool m = (t < len[b]);
                    long hidx = (long)b * HN_ + u;
                    float c_old = g_c[seq][b][u];
                    float nc = c_old * sigmoidf_(fv + 1.0f) + sigmoidf_(iv) * tanhf(jv);
                    float nh = tanhf(nc) * sigmoidf_(ov);
                    g_c[seq][b][u] = m ? nc : c_old;
                    __half hh, hl;
                    if (m) {
                        hh = __float2half(nh);
                        hl = __float2half(nh - __half2float(hh));
                    } else {
                        hh = g_hhi[hin_base + hidx];
                        hl = g_hlo[hin_base + hidx];
                    }
                    g_hhi[hout_base + hidx] = hh;
                    g_hlo[hout_base + hidx] = hl;
                }
            }
        }
    }
}

// ---------------------------------------------------------------------------
// MLP head (fp32)
__global__ void gather_x_kernel() {
    int i = blockIdx.x * blockDim.x + threadIdx.x;
    if (i >= BN_ * FOURH) return;
    int b   = i >> 11;
    int col = i & 2047;
    g_x[i] = g_c[col >> 9][b][col & 511];
}

#define BMT 64
#define BUT 64
#define KT  16
__global__ __launch_bounds__(256) void mlp_gemm_kernel(const float* __restrict__ W,
                                                       const float* __restrict__ bias,
                                                       int layer) {
    const float* A; float* C; int K, N;
    if (layer == 1)      { A = g_x;  C = g_m1; K = 2048; N = 1024; }
    else if (layer == 2) { A = g_m1; C = g_m2; K = 1024; N = 1024; }
    else                 { A = g_m2; C = g_m3; K = 1024; N = 1024; }

    const int m0 = blockIdx.y * BMT;
    const int n0 = blockIdx.x * BUT;
    __shared__ float As[KT][BMT];
    __shared__ float Bs[KT][BUT];
    const int tid = threadIdx.x;
    const int r0  = (tid >> 4) * 4;
    const int nt0 = (tid & 15) * 4;

    float acc[4][4];
    #pragma unroll
    for (int r = 0; r < 4; r++)
        #pragma unroll
        for (int u = 0; u < 4; u++) acc[r][u] = 0.0f;

    for (int k0 = 0; k0 < K; k0 += KT) {
        {
            int r  = tid >> 2;
            int kq = (tid & 3) * 4;
            #pragma unroll
            for (int i = 0; i < 4; i++)
                As[kq + i][r] = A[(m0 + r) * K + k0 + kq + i];
        }
        {
            int kk = tid >> 4;
            int uu = (tid & 15) * 4;
            *(float4*)&Bs[kk][uu] = *(const float4*)(W + (k0 + kk) * N + n0 + uu);
        }
        __syncthreads();
        #pragma unroll
        for (int kk = 0; kk < KT; kk++) {
            float4 a4 = *(const float4*)&As[kk][r0];
            float4 b4 = *(const float4*)&Bs[kk][nt0];
            float av[4] = {a4.x, a4.y, a4.z, a4.w};
            float bv[4] = {b4.x, b4.y, b4.z, b4.w};
            #pragma unroll
            for (int r = 0; r < 4; r++)
                #pragma unroll
                for (int u = 0; u < 4; u++)
                    acc[r][u] = fmaf(av[r], bv[u], acc[r][u]);
        }
        __syncthreads();
    }
    #pragma unroll
    for (int r = 0; r < 4; r++)
        #pragma unroll
        for (int u = 0; u < 4; u++) {
            int n = n0 + nt0 + u;
            C[(m0 + r0 + r) * N + n] = tanhf(acc[r][u] + bias[n]);
        }
}

__global__ void final_logits_kernel(const float* __restrict__ W4,
                                    const float* __restrict__ b4,
                                    float* __restrict__ out) {
    int b    = blockIdx.x;
    int w    = threadIdx.x >> 5;
    int lane = threadIdx.x & 31;
    if (w >= 3) return;
    float sum = 0.0f;
    for (int k = lane; k < 1024; k += 32)
        sum += g_m3[b * 1024 + k] * W4[k * 3 + w];
    #pragma unroll
    for (int off = 16; off; off >>= 1)
        sum += __shfl_down_sync(0xffffffff, sum, off);
    if (lane == 0) out[b * 3 + w] = sum + b4[w];
}

// ---------------------------------------------------------------------------
extern "C" void kernel_launch(void* const* d_in, const int* in_sizes, int n_in,
                              void* d_out, int out_size) {
    const float* premises   = (const float*)d_in[0];
    const float* hypotheses = (const float*)d_in[1];
    const int*   plen       = (const int*)d_in[2];
    const int*   hlen       = (const int*)d_in[3];

    WPtrs wp;
    for (int i = 0; i < 4; i++) {
        wp.wx[i]   = (const float*)d_in[4 + 3 * i + 0];
        wp.wh[i]   = (const float*)d_in[4 + 3 * i + 1];
        wp.bias[i] = (const float*)d_in[4 + 3 * i + 2];
    }
    const float* W1 = (const float*)d_in[16];
    const float* b1 = (const float*)d_in[17];
    const float* W2 = (const float*)d_in[18];
    const float* b2 = (const float*)d_in[19];
    const float* W3 = (const float*)d_in[20];
    const float* b3 = (const float*)d_in[21];
    const float* W4 = (const float*)d_in[22];
    const float* b4 = (const float*)d_in[23];
    float* out = (float*)d_out;

    cudaFuncSetAttribute(lstm_step_mma, cudaFuncAttributeMaxDynamicSharedMemorySize,
                         SMEM_TOTAL_STEP);

    // ONE preprocessing launch (ncu -s 5 then lands on lstm_step #5)
    {
        long long n = NTOT_;
        preproc_all<<<(unsigned)((n + 255) / 256), 256>>>(premises, hypotheses, wp);
    }

    // recurrence
    dim3 grid(16, 2, 4);
    for (int s = 0; s < TN_; s++)
        lstm_step_mma<<<grid, 256, SMEM_TOTAL_STEP>>>(plen, hlen, s);

    // MLP head
    gather_x_kernel<<<(BN_ * FOURH + 255) / 256, 256>>>();
    mlp_gemm_kernel<<<dim3(1024 / BUT, BN_ / BMT), 256>>>(W1, b1, 1);
    mlp_gemm_kernel<<<dim3(1024 / BUT, BN_ / BMT), 256>>>(W2, b2, 2);
    mlp_gemm_kernel<<<dim3(1024 / BUT, BN_ / BMT), 256>>>(W3, b3, 3);
    final_logits_kernel<<<BN_, 96>>>(W4, b4, out);
}

// round 6
// speedup vs baseline: 1.1843x; 1.1843x over previous
#include <cuda_runtime.h>
#include <cuda_fp16.h>
#include <math.h>
#include <stdint.h>

// ---------------------------------------------------------------------------
// Problem constants
#define BN_   256   // batch
#define TN_   256   // time steps
#define DN_   300   // input dim
#define HN_   512   // hidden
#define XPAD  320   // x padded to 320 (5 chunks of 64)
#define KPAD  832   // 300 + 512 fused K, padded
#define NCHUNK 13   // 832 / 64
#define FOURH 2048

// ---------------------------------------------------------------------------
// Scratch (device globals) — inputs pre-split into fp16 hi/lo arrays
__device__ __half g_xhi[2ll * BN_ * TN_ * XPAD];
__device__ __half g_xlo[2ll * BN_ * TN_ * XPAD];
__device__ __half g_whi[4ll * FOURH * KPAD];
__device__ __half g_wlo[4ll * FOURH * KPAD];
__device__ float  g_bp [4 * FOURH];                 // permuted bias
__device__ __half g_hhi[2ll * 4 * BN_ * HN_];       // double-buffered h hi
__device__ __half g_hlo[2ll * 4 * BN_ * HN_];       // double-buffered h lo
__device__ float  g_c  [4][BN_][HN_];               // cell state
__device__ float  g_x  [BN_ * FOURH];               // concat c -> MLP input
__device__ float  g_m1[BN_ * 1024];
__device__ float  g_m2[BN_ * 1024];
__device__ float  g_m3[BN_ * 1024];

__device__ __forceinline__ float sigmoidf_(float v) { return 1.0f / (1.0f + expf(-v)); }

__device__ __forceinline__ uint32_t smem_u32(const void* p) {
    uint32_t a;
    asm("{ .reg .u64 t; cvta.to.shared.u64 t, %1; cvt.u32.u64 %0, t; }" : "=r"(a) : "l"(p));
    return a;
}
__device__ __forceinline__ void cp16(uint32_t dst, const void* src) {
    asm volatile("cp.async.cg.shared.global [%0], [%1], 16;" :: "r"(dst), "l"(src));
}
#define CP_COMMIT() asm volatile("cp.async.commit_group;" ::: "memory")
#define CP_WAIT(N)  asm volatile("cp.async.wait_group %0;" :: "n"(N) : "memory")

#define LDSM_X4(r0, r1, r2, r3, addr)                                         \
    asm volatile("ldmatrix.sync.aligned.m8n8.x4.shared.b16 {%0,%1,%2,%3}, [%4];" \
        : "=r"(r0), "=r"(r1), "=r"(r2), "=r"(r3) : "r"(addr))

// f32-accumulate HMMA (main product)
#define MMA16816(d, a, b)                                                     \
    asm volatile("mma.sync.aligned.m16n8k16.row.col.f32.f16.f16.f32 "         \
        "{%0,%1,%2,%3}, {%4,%5,%6,%7}, {%8,%9}, {%0,%1,%2,%3};"               \
        : "+f"((d)[0]), "+f"((d)[1]), "+f"((d)[2]), "+f"((d)[3])              \
        : "r"((a)[0]), "r"((a)[1]), "r"((a)[2]), "r"((a)[3]),                 \
          "r"((b)[0]), "r"((b)[1]))

// f16-accumulate HMMA (correction products; d = 2x f16x2 regs)
#define MMA16816H(d, a, b)                                                    \
    asm volatile("mma.sync.aligned.m16n8k16.row.col.f16.f16.f16.f16 "         \
        "{%0,%1}, {%2,%3,%4,%5}, {%6,%7}, {%0,%1};"                           \
        : "+r"((d)[0]), "+r"((d)[1])                                          \
        : "r"((a)[0]), "r"((a)[1]), "r"((a)[2]), "r"((a)[3]),                 \
          "r"((b)[0]), "r"((b)[1]))

// ---------------------------------------------------------------------------
// Fused one-shot preprocessing (single launch)
struct WPtrs { const float* wx[4]; const float* wh[4]; const float* bias[4]; };

#define NX_ (2ll * BN_ * TN_ * XPAD)
#define NW_ (4ll * FOURH * KPAD)
#define NH_ (2ll * 4 * BN_ * HN_)
#define NC_ (4ll * BN_ * HN_)
#define NB_ (4ll * FOURH)
#define NTOT_ (NX_ + NW_ + NH_ + NC_ + NB_)

__global__ void preproc_all(const float* __restrict__ prem, const float* __restrict__ hyp,
                            WPtrs wp) {
    long long i = (long long)blockIdx.x * blockDim.x + threadIdx.x;
    if (i < NX_) {                                   // x -> hi/lo split, padded
        int k = (int)(i % XPAD);
        long long r = i / XPAD;
        int t = (int)(r % TN_); r /= TN_;
        int b = (int)(r % BN_);
        int inp = (int)(r / BN_);
        float v = 0.0f;
        if (k < DN_) {
            const float* src = inp ? hyp : prem;
            v = src[((long long)b * TN_ + t) * DN_ + k];
        }
        __half h = __float2half(v);
        g_xhi[i] = h;
        g_xlo[i] = __float2half(v - __half2float(h));
        return;
    }
    i -= NX_;
    if (i < NW_) {                                   // W -> permuted/transposed hi/lo
        int kp = (int)(i % KPAD);
        long long r = i / KPAD;
        int c   = (int)(r % FOURH);
        int seq = (int)(r / FOURH);
        int oc  = (c & 3) * HN_ + (c >> 2);          // gate-interleaved col' = u*4+g
        float v = 0.0f;
        if (kp < DN_)        v = wp.wx[seq][(long long)kp * FOURH + oc];
        else if (kp >= XPAD) v = wp.wh[seq][(long long)(kp - XPAD) * FOURH + oc];
        __half h = __float2half(v);
        g_whi[i] = h;
        g_wlo[i] = __float2half(v - __half2float(h));
        return;
    }
    i -= NW_;
    if (i < NH_) {                                   // zero h buffers
        g_hhi[i] = __float2half(0.f);
        g_hlo[i] = __float2half(0.f);
        return;
    }
    i -= NH_;
    if (i < NC_) {                                   // zero c
        (&g_c[0][0][0])[i] = 0.0f;
        return;
    }
    i -= NC_;
    if (i < NB_) {                                   // permuted bias
        int c = (int)(i & (FOURH - 1));
        int seq = (int)(i >> 11);
        g_bp[i] = wp.bias[seq][(c & 3) * HN_ + (c >> 2)];
    }
}

// ---------------------------------------------------------------------------
// Fused LSTM step via mma.sync. 512 threads = 16 warps (4m x 4n), warp tile
// 32x32 -> 4 warps per SMSP for latency hiding. fp16 hi/lo split:
// main product f32-acc, corrections f16-acc.
#define ST_BYTES 65536
#define OFF_AL   16384
#define OFF_BH   32768
#define OFF_BL   49152
#define OFF_BIAS 131072
#define SMEM_TOTAL_STEP 131584

__global__ __launch_bounds__(512) void lstm_step_mma(const int* __restrict__ plen,
                                                     const int* __restrict__ hlen,
                                                     int s) {
    extern __shared__ char smem[];
    const uint32_t sbase = smem_u32(smem);
    const int tid  = threadIdx.x;
    const int lane = tid & 31;
    const int wid  = tid >> 5;
    const int warp_m = wid >> 2;       // 0..3 (32 rows each)
    const int warp_n = wid & 3;        // 0..3 (32 cols each)

    const int seq = blockIdx.z;
    const int rev = seq & 1;
    const int t   = rev ? (TN_ - 1 - s) : s;
    const int inp = seq >> 1;
    const int b0  = blockIdx.y * 128;
    const int n0  = blockIdx.x * 128;
    const int cur = s & 1;

    if (tid < 128)
        *(float*)(smem + OFF_BIAS + tid * 4) = g_bp[seq * FOURH + n0 + tid];

    const long hin_base  = ((long)cur * 4 + seq) * (BN_ * HN_);
    const long hout_base = ((long)(cur ^ 1) * 4 + seq) * (BN_ * HN_);

    // ---- chunk loader (cp.async): 512 threads, 2 iters per array ----------
    auto load_chunk = [&](int k, int p) {
        const uint32_t st = sbase + (p ? ST_BYTES : 0);
        const bool isx = (k < 5);
        const int k0 = k * 64;
        #pragma unroll
        for (int j = 0; j < 2; j++) {           // A: hi + lo
            int idx = tid + 512 * j;            // 0..1023
            int row = idx >> 3;
            int seg = idx & 7;
            int kk  = k0 + seg * 8;
            long base;
            if (isx) base = ((long)(inp * BN_ + b0 + row) * TN_ + t) * XPAD + kk;
            else     base = hin_base + (long)(b0 + row) * HN_ + (kk - XPAD);
            uint32_t dst = st + ((row * 8 + (seg ^ (row & 7))) << 4);
            cp16(dst,          isx ? (const void*)(g_xhi + base) : (const void*)(g_hhi + base));
            cp16(dst + OFF_AL, isx ? (const void*)(g_xlo + base) : (const void*)(g_hlo + base));
        }
        #pragma unroll
        for (int j = 0; j < 2; j++) {           // B: hi + lo
            int idx = tid + 512 * j;
            int row = idx >> 3;
            int seg = idx & 7;
            int kk  = k0 + seg * 8;
            long base = ((long)seq * FOURH + n0 + row) * KPAD + kk;
            uint32_t dst = st + OFF_BH + ((row * 8 + (seg ^ (row & 7))) << 4);
            cp16(dst,         g_whi + base);
            cp16(dst + 16384, g_wlo + base);
        }
        CP_COMMIT();
    };

    // accumulators: main f32 [mi][ni][4], corrections f16x2 [mi][ni][2]
    float acc[2][4][4];
    uint32_t acch[2][4][2];
    #pragma unroll
    for (int mi = 0; mi < 2; mi++)
        #pragma unroll
        for (int ni = 0; ni < 4; ni++) {
            #pragma unroll
            for (int q = 0; q < 4; q++) acc[mi][ni][q] = 0.0f;
            acch[mi][ni][0] = 0u; acch[mi][ni][1] = 0u;
        }

    // per-lane ldmatrix row invariants
    int arowb[2], arowx[2];
    #pragma unroll
    for (int mi = 0; mi < 2; mi++) {
        int r = warp_m * 32 + mi * 16 + (lane & 15);
        arowb[mi] = r * 128;
        arowx[mi] = r & 7;
    }
    int brow[2], browx[2];
    #pragma unroll
    for (int np = 0; np < 2; np++) {
        int n = warp_n * 32 + np * 16 + ((lane >> 4) << 3) + (lane & 7);
        brow[np]  = n * 128;
        browx[np] = n & 7;
    }
    const int asel = lane >> 4;          // 0/1 -> k or k+8 half for A
    const int bsel = (lane >> 3) & 1;    // 0/1 -> k or k+8 half for B

    load_chunk(0, 0);

    for (int k = 0; k < NCHUNK; k++) {
        const int p = k & 1;
        if (k + 1 < NCHUNK) load_chunk(k + 1, p ^ 1);
        if (k + 1 < NCHUNK) CP_WAIT(1); else CP_WAIT(0);
        __syncthreads();

        const uint32_t st = sbase + (p ? ST_BYTES : 0);
        #pragma unroll
        for (int kk = 0; kk < 4; kk++) {
            uint32_t ah[2][4], al[2][4];
            #pragma unroll
            for (int mi = 0; mi < 2; mi++) {
                int seg = 2 * kk + asel;
                uint32_t off = arowb[mi] + ((seg ^ arowx[mi]) << 4);
                LDSM_X4(ah[mi][0], ah[mi][1], ah[mi][2], ah[mi][3], st + off);
                LDSM_X4(al[mi][0], al[mi][1], al[mi][2], al[mi][3], st + OFF_AL + off);
            }
            uint32_t bh[2][4], bl[2][4];
            #pragma unroll
            for (int np = 0; np < 2; np++) {
                int seg = 2 * kk + bsel;
                uint32_t off = brow[np] + ((seg ^ browx[np]) << 4);
                LDSM_X4(bh[np][0], bh[np][1], bh[np][2], bh[np][3], st + OFF_BH + off);
                LDSM_X4(bl[np][0], bl[np][1], bl[np][2], bl[np][3], st + OFF_BL + off);
            }
            #pragma unroll
            for (int mi = 0; mi < 2; mi++)
                #pragma unroll
                for (int np = 0; np < 2; np++)
                    #pragma unroll
                    for (int h = 0; h < 2; h++) {
                        int ni = np * 2 + h;
                        uint32_t bhf[2] = { bh[np][2 * h], bh[np][2 * h + 1] };
                        uint32_t blf[2] = { bl[np][2 * h], bl[np][2 * h + 1] };
                        MMA16816 (acc[mi][ni],  ah[mi], bhf);   // main, f32 acc
                        MMA16816H(acch[mi][ni], ah[mi], blf);   // corr, f16 acc
                        MMA16816H(acch[mi][ni], al[mi], bhf);   // corr, f16 acc
                    }
        }
        __syncthreads();
    }

    // ---- epilogue: merge corrections, gates + masked state update ---------
    const int* __restrict__ len = (seq < 2) ? plen : hlen;
    const float* bias_s = (const float*)(smem + OFF_BIAS);
    const bool amain = ((lane & 1) == 0);

    #pragma unroll
    for (int mi = 0; mi < 2; mi++) {
        #pragma unroll
        for (int ni = 0; ni < 4; ni++) {
            float2 c01 = __half22float2(*(__half2*)&acch[mi][ni][0]);
            float2 c23 = __half22float2(*(__half2*)&acch[mi][ni][1]);
            int col_local = warp_n * 32 + ni * 8 + 2 * (lane & 3);
            float v0 = acc[mi][ni][0] + c01.x + bias_s[col_local];
            float v1 = acc[mi][ni][1] + c01.y + bias_s[col_local + 1];
            float v2 = acc[mi][ni][2] + c23.x + bias_s[col_local];
            float v3 = acc[mi][ni][3] + c23.y + bias_s[col_local + 1];
            float p0 = __shfl_xor_sync(0xffffffffu, v0, 1);
            float p1 = __shfl_xor_sync(0xffffffffu, v1, 1);
            float p2 = __shfl_xor_sync(0xffffffffu, v2, 1);
            float p3 = __shfl_xor_sync(0xffffffffu, v3, 1);
            if (amain) {
                int u = (n0 + col_local) >> 2;
                #pragma unroll
                for (int rh = 0; rh < 2; rh++) {
                    int b = b0 + warp_m * 32 + mi * 16 + (lane >> 2) + rh * 8;
                    float iv = rh ? v2 : v0;
                    float jv = rh ? v3 : v1;
                    float fv = rh ? p2 : p0;
                    float ov = rh ? p3 : p1;
                    bool m = (t < len[b]);
                    long hidx = (long)b * HN_ + u;
                    float c_old = g_c[seq][b][u];
                    float nc = c_old * sigmoidf_(fv + 1.0f) + sigmoidf_(iv) * tanhf(jv);
                    float nh = tanhf(nc) * sigmoidf_(ov);
                    g_c[seq][b][u] = m ? nc : c_old;
                    __half hh, hl;
                    if (m) {
                        hh = __float2half(nh);
                        hl = __float2half(nh - __half2float(hh));
                    } else {
                        hh = g_hhi[hin_base + hidx];
                        hl = g_hlo[hin_base + hidx];
                    }
                    g_hhi[hout_base + hidx] = hh;
                    g_hlo[hout_base + hidx] = hl;
                }
            }
        }
    }
}

// ---------------------------------------------------------------------------
// MLP head (fp32)
__global__ void gather_x_kernel() {
    int i = blockIdx.x * blockDim.x + threadIdx.x;
    if (i >= BN_ * FOURH) return;
    int b   = i >> 11;
    int col = i & 2047;
    g_x[i] = g_c[col >> 9][b][col & 511];
}

#define BMT 64
#define BUT 64
#define KT  16
__global__ __launch_bounds__(256) void mlp_gemm_kernel(const float* __restrict__ W,
                                                       const float* __restrict__ bias,
                                                       int layer) {
    const float* A; float* C; int K, N;
    if (layer == 1)      { A = g_x;  C = g_m1; K = 2048; N = 1024; }
    else if (layer == 2) { A = g_m1; C = g_m2; K = 1024; N = 1024; }
    else                 { A = g_m2; C = g_m3; K = 1024; N = 1024; }

    const int m0 = blockIdx.y * BMT;
    const int n0 = blockIdx.x * BUT;
    __shared__ float As[KT][BMT];
    __shared__ float Bs[KT][BUT];
    const int tid = threadIdx.x;
    const int r0  = (tid >> 4) * 4;
    const int nt0 = (tid & 15) * 4;

    float acc[4][4];
    #pragma unroll
    for (int r = 0; r < 4; r++)
        #pragma unroll
        for (int u = 0; u < 4; u++) acc[r][u] = 0.0f;

    for (int k0 = 0; k0 < K; k0 += KT) {
        {
            int r  = tid >> 2;
            int kq = (tid & 3) * 4;
            #pragma unroll
            for (int i = 0; i < 4; i++)
                As[kq + i][r] = A[(m0 + r) * K + k0 + kq + i];
        }
        {
            int kk = tid >> 4;
            int uu = (tid & 15) * 4;
            *(float4*)&Bs[kk][uu] = *(const float4*)(W + (k0 + kk) * N + n0 + uu);
        }
        __syncthreads();
        #pragma unroll
        for (int kk = 0; kk < KT; kk++) {
            float4 a4 = *(const float4*)&As[kk][r0];
            float4 b4 = *(const float4*)&Bs[kk][nt0];
            float av[4] = {a4.x, a4.y, a4.z, a4.w};
            float bv[4] = {b4.x, b4.y, b4.z, b4.w};
            #pragma unroll
            for (int r = 0; r < 4; r++)
                #pragma unroll
                for (int u = 0; u < 4; u++)
                    acc[r][u] = fmaf(av[r], bv[u], acc[r][u]);
        }
        __syncthreads();
    }
    #pragma unroll
    for (int r = 0; r < 4; r++)
        #pragma unroll
        for (int u = 0; u < 4; u++) {
            int n = n0 + nt0 + u;
            C[(m0 + r0 + r) * N + n] = tanhf(acc[r][u] + bias[n]);
        }
}

__global__ void final_logits_kernel(const float* __restrict__ W4,
                                    const float* __restrict__ b4,
                                    float* __restrict__ out) {
    int b    = blockIdx.x;
    int w    = threadIdx.x >> 5;
    int lane = threadIdx.x & 31;
    if (w >= 3) return;
    float sum = 0.0f;
    for (int k = lane; k < 1024; k += 32)
        sum += g_m3[b * 1024 + k] * W4[k * 3 + w];
    #pragma unroll
    for (int off = 16; off; off >>= 1)
        sum += __shfl_down_sync(0xffffffff, sum, off);
    if (lane == 0) out[b * 3 + w] = sum + b4[w];
}

// ---------------------------------------------------------------------------
extern "C" void kernel_launch(void* const* d_in, const int* in_sizes, int n_in,
                              void* d_out, int out_size) {
    const float* premises   = (const float*)d_in[0];
    const float* hypotheses = (const float*)d_in[1];
    const int*   plen       = (const int*)d_in[2];
    const int*   hlen       = (const int*)d_in[3];

    WPtrs wp;
    for (int i = 0; i < 4; i++) {
        wp.wx[i]   = (const float*)d_in[4 + 3 * i + 0];
        wp.wh[i]   = (const float*)d_in[4 + 3 * i + 1];
        wp.bias[i] = (const float*)d_in[4 + 3 * i + 2];
    }
    const float* W1 = (const float*)d_in[16];
    const float* b1 = (const float*)d_in[17];
    const float* W2 = (const float*)d_in[18];
    const float* b2 = (const float*)d_in[19];
    const float* W3 = (const float*)d_in[20];
    const float* b3 = (const float*)d_in[21];
    const float* W4 = (const float*)d_in[22];
    const float* b4 = (const float*)d_in[23];
    float* out = (float*)d_out;

    cudaFuncSetAttribute(lstm_step_mma, cudaFuncAttributeMaxDynamicSharedMemorySize,
                         SMEM_TOTAL_STEP);

    // ONE preprocessing launch
    {
        long long n = NTOT_;
        preproc_all<<<(unsigned)((n + 255) / 256), 256>>>(premises, hypotheses, wp);
    }

    // recurrence
    dim3 grid(16, 2, 4);
    for (int s = 0; s < TN_; s++)
        lstm_step_mma<<<grid, 512, SMEM_TOTAL_STEP>>>(plen, hlen, s);

    // MLP head
    gather_x_kernel<<<(BN_ * FOURH + 255) / 256, 256>>>();
    mlp_gemm_kernel<<<dim3(1024 / BUT, BN_ / BMT), 256>>>(W1, b1, 1);
    mlp_gemm_kernel<<<dim3(1024 / BUT, BN_ / BMT), 256>>>(W2, b2, 2);
    mlp_gemm_kernel<<<dim3(1024 / BUT, BN_ / BMT), 256>>>(W3, b3, 3);
    final_logits_kernel<<<BN_, 96>>>(W4, b4, out);
}

// round 7
// speedup vs baseline: 1.1879x; 1.0030x over previous
#include <cuda_runtime.h>
#include <cuda_fp16.h>
#include <math.h>
#include <stdint.h>

// ---------------------------------------------------------------------------
// Problem constants
#define BN_   256   // batch
#define TN_   256   // time steps
#define DN_   300   // input dim
#define HN_   512   // hidden
#define XPAD  320   // x padded to 320 (5 chunks of 64)
#define KPAD  832   // 320 + 512 (W layout rows)
#define NCHX  5     // x chunks (precompute GEMM)
#define NCHS  8     // h chunks (per-step GEMM, K=512)
#define FOURH 2048

// ---------------------------------------------------------------------------
// Scratch (device globals)
__device__ __half g_xhi[2ll * BN_ * TN_ * XPAD];
__device__ __half g_xlo[2ll * BN_ * TN_ * XPAD];
__device__ __half g_whi[4ll * FOURH * KPAD];
__device__ __half g_wlo[4ll * FOURH * KPAD];
__device__ float  g_bp [4 * FOURH];                 // permuted bias
__device__ __half g_hhi[2ll * 4 * BN_ * HN_];       // double-buffered h hi
__device__ __half g_hlo[2ll * 4 * BN_ * HN_];       // double-buffered h lo
__device__ float  g_c  [4][BN_][HN_];               // cell state
__device__ float  g_x  [BN_ * FOURH];               // concat c -> MLP input
__device__ float  g_m1[BN_ * 1024];
__device__ float  g_m2[BN_ * 1024];
__device__ float  g_m3[BN_ * 1024];

// Precomputed x-projections: xz[seq][t][b][n], fp32. Split into two 1 GiB
// arrays (seq 0-1 / seq 2-3) to stay under per-array size limits.
#define XZ_PER (2ll * TN_ * BN_ * FOURH)            // 268,435,456 floats
__device__ float g_xzA[XZ_PER];
__device__ float g_xzB[XZ_PER];

__device__ __forceinline__ float sigmoidf_(float v) { return 1.0f / (1.0f + expf(-v)); }

__device__ __forceinline__ uint32_t smem_u32(const void* p) {
    uint32_t a;
    asm("{ .reg .u64 t; cvta.to.shared.u64 t, %1; cvt.u32.u64 %0, t; }" : "=r"(a) : "l"(p));
    return a;
}
__device__ __forceinline__ void cp16(uint32_t dst, const void* src) {
    asm volatile("cp.async.cg.shared.global [%0], [%1], 16;" :: "r"(dst), "l"(src));
}
#define CP_COMMIT() asm volatile("cp.async.commit_group;" ::: "memory")
#define CP_WAIT(N)  asm volatile("cp.async.wait_group %0;" :: "n"(N) : "memory")

#define LDSM_X4(r0, r1, r2, r3, addr)                                         \
    asm volatile("ldmatrix.sync.aligned.m8n8.x4.shared.b16 {%0,%1,%2,%3}, [%4];" \
        : "=r"(r0), "=r"(r1), "=r"(r2), "=r"(r3) : "r"(addr))

// f32-accumulate HMMA (main product)
#define MMA16816(d, a, b)                                                     \
    asm volatile("mma.sync.aligned.m16n8k16.row.col.f32.f16.f16.f32 "         \
        "{%0,%1,%2,%3}, {%4,%5,%6,%7}, {%8,%9}, {%0,%1,%2,%3};"               \
        : "+f"((d)[0]), "+f"((d)[1]), "+f"((d)[2]), "+f"((d)[3])              \
        : "r"((a)[0]), "r"((a)[1]), "r"((a)[2]), "r"((a)[3]),                 \
          "r"((b)[0]), "r"((b)[1]))

// f16-accumulate HMMA (correction products)
#define MMA16816H(d, a, b)                                                    \
    asm volatile("mma.sync.aligned.m16n8k16.row.col.f16.f16.f16.f16 "         \
        "{%0,%1}, {%2,%3,%4,%5}, {%6,%7}, {%0,%1};"                           \
        : "+r"((d)[0]), "+r"((d)[1])                                          \
        : "r"((a)[0]), "r"((a)[1]), "r"((a)[2]), "r"((a)[3]),                 \
          "r"((b)[0]), "r"((b)[1]))

// ---------------------------------------------------------------------------
// Fused one-shot preprocessing (single launch)
struct WPtrs { const float* wx[4]; const float* wh[4]; const float* bias[4]; };

#define NXE_ (2ll * BN_ * TN_ * XPAD)
#define NWE_ (4ll * FOURH * KPAD)
#define NHE_ (2ll * 4 * BN_ * HN_)
#define NCE_ (4ll * BN_ * HN_)
#define NBE_ (4ll * FOURH)
#define NTOT_ (NXE_ + NWE_ + NHE_ + NCE_ + NBE_)

__global__ void preproc_all(const float* __restrict__ prem, const float* __restrict__ hyp,
                            WPtrs wp) {
    long long i = (long long)blockIdx.x * blockDim.x + threadIdx.x;
    if (i < NXE_) {
        int k = (int)(i % XPAD);
        long long r = i / XPAD;
        int t = (int)(r % TN_); r /= TN_;
        int b = (int)(r % BN_);
        int inp = (int)(r / BN_);
        float v = 0.0f;
        if (k < DN_) {
            const float* src = inp ? hyp : prem;
            v = src[((long long)b * TN_ + t) * DN_ + k];
        }
        __half h = __float2half(v);
        g_xhi[i] = h;
        g_xlo[i] = __float2half(v - __half2float(h));
        return;
    }
    i -= NXE_;
    if (i < NWE_) {
        int kp = (int)(i % KPAD);
        long long r = i / KPAD;
        int c   = (int)(r % FOURH);
        int seq = (int)(r / FOURH);
        int oc  = (c & 3) * HN_ + (c >> 2);          // gate-interleaved col' = u*4+g
        float v = 0.0f;
        if (kp < DN_)        v = wp.wx[seq][(long long)kp * FOURH + oc];
        else if (kp >= XPAD) v = wp.wh[seq][(long long)(kp - XPAD) * FOURH + oc];
        __half h = __float2half(v);
        g_whi[i] = h;
        g_wlo[i] = __float2half(v - __half2float(h));
        return;
    }
    i -= NWE_;
    if (i < NHE_) {
        g_hhi[i] = __float2half(0.f);
        g_hlo[i] = __float2half(0.f);
        return;
    }
    i -= NHE_;
    if (i < NCE_) {
        (&g_c[0][0][0])[i] = 0.0f;
        return;
    }
    i -= NCE_;
    if (i < NBE_) {
        int c = (int)(i & (FOURH - 1));
        int seq = (int)(i >> 11);
        g_bp[i] = wp.bias[seq][(c & 3) * HN_ + (c >> 2)];
    }
}

// ---------------------------------------------------------------------------
// xz precompute GEMM: xz[seq][t][b][n] = x[b,t,:] @ Wx_seq (fp16 hi/lo split).
// Tile 128(b) x 64(n), 256 threads = 8 warps (4m x 2n), warp tile 32x32.
// 2 CTAs/SM resident (regs 256*126=32K, smem 96K) so overheads overlap.
#define XST_BYTES 49152
#define XOFF_AL   16384
#define XOFF_BH   32768
#define XOFF_BL   40960
#define SMEM_XZ   98304

__global__ __launch_bounds__(256) void xz_gemm() {
    extern __shared__ char smem[];
    const uint32_t sbase = smem_u32(smem);
    const int tid  = threadIdx.x;
    const int lane = tid & 31;
    const int wid  = tid >> 5;
    const int warp_m = wid >> 1;       // 0..3
    const int warp_n = wid & 1;        // 0..1

    const int z   = blockIdx.z;        // seq*TN_ + t
    const int seq = z >> 8;
    const int t   = z & 255;
    const int inp = seq >> 1;
    const int b0  = blockIdx.y * 128;
    const int n0  = blockIdx.x * 64;

    auto load_chunk = [&](int k, int p) {
        const uint32_t st = sbase + (p ? XST_BYTES : 0);
        const int k0 = k * 64;
        #pragma unroll
        for (int j = 0; j < 4; j++) {           // A: 1024 segs, hi + lo
            int idx = tid + 256 * j;
            int row = idx >> 3;
            int seg = idx & 7;
            long base = ((long)(inp * BN_ + b0 + row) * TN_ + t) * XPAD + k0 + seg * 8;
            uint32_t dst = st + ((row * 8 + (seg ^ (row & 7))) << 4);
            cp16(dst,           g_xhi + base);
            cp16(dst + XOFF_AL, g_xlo + base);
        }
        #pragma unroll
        for (int j = 0; j < 2; j++) {           // B: 512 segs, hi + lo
            int idx = tid + 256 * j;
            int row = idx >> 3;
            int seg = idx & 7;
            long base = ((long)seq * FOURH + n0 + row) * KPAD + k0 + seg * 8;
            uint32_t dst = st + XOFF_BH + ((row * 8 + (seg ^ (row & 7))) << 4);
            cp16(dst,        g_whi + base);
            cp16(dst + 8192, g_wlo + base);
        }
        CP_COMMIT();
    };

    float acc[2][4][4];
    uint32_t acch[2][4][2];
    #pragma unroll
    for (int mi = 0; mi < 2; mi++)
        #pragma unroll
        for (int ni = 0; ni < 4; ni++) {
            #pragma unroll
            for (int q = 0; q < 4; q++) acc[mi][ni][q] = 0.0f;
            acch[mi][ni][0] = 0u; acch[mi][ni][1] = 0u;
        }

    int arowb[2], arowx[2];
    #pragma unroll
    for (int mi = 0; mi < 2; mi++) {
        int r = warp_m * 32 + mi * 16 + (lane & 15);
        arowb[mi] = r * 128;
        arowx[mi] = r & 7;
    }
    int brow[2], browx[2];
    #pragma unroll
    for (int np = 0; np < 2; np++) {
        int n = warp_n * 32 + np * 16 + ((lane >> 4) << 3) + (lane & 7);
        brow[np]  = n * 128;
        browx[np] = n & 7;
    }
    const int asel = lane >> 4;
    const int bsel = (lane >> 3) & 1;

    load_chunk(0, 0);

    for (int k = 0; k < NCHX; k++) {
        const int p = k & 1;
        if (k + 1 < NCHX) load_chunk(k + 1, p ^ 1);
        if (k + 1 < NCHX) CP_WAIT(1); else CP_WAIT(0);
        __syncthreads();

        const uint32_t st = sbase + (p ? XST_BYTES : 0);
        #pragma unroll
        for (int kk = 0; kk < 4; kk++) {
            uint32_t ah[2][4], al[2][4];
            #pragma unroll
            for (int mi = 0; mi < 2; mi++) {
                int seg = 2 * kk + asel;
                uint32_t off = arowb[mi] + ((seg ^ arowx[mi]) << 4);
                LDSM_X4(ah[mi][0], ah[mi][1], ah[mi][2], ah[mi][3], st + off);
                LDSM_X4(al[mi][0], al[mi][1], al[mi][2], al[mi][3], st + XOFF_AL + off);
            }
            uint32_t bh[2][4], bl[2][4];
            #pragma unroll
            for (int np = 0; np < 2; np++) {
                int seg = 2 * kk + bsel;
                uint32_t off = brow[np] + ((seg ^ browx[np]) << 4);
                LDSM_X4(bh[np][0], bh[np][1], bh[np][2], bh[np][3], st + XOFF_BH + off);
                LDSM_X4(bl[np][0], bl[np][1], bl[np][2], bl[np][3], st + XOFF_BL + off);
            }
            #pragma unroll
            for (int mi = 0; mi < 2; mi++)
                #pragma unroll
                for (int np = 0; np < 2; np++)
                    #pragma unroll
                    for (int h = 0; h < 2; h++) {
                        int ni = np * 2 + h;
                        uint32_t bhf[2] = { bh[np][2 * h], bh[np][2 * h + 1] };
                        uint32_t blf[2] = { bl[np][2 * h], bl[np][2 * h + 1] };
                        MMA16816 (acc[mi][ni],  ah[mi], bhf);
                        MMA16816H(acch[mi][ni], ah[mi], blf);
                        MMA16816H(acch[mi][ni], al[mi], bhf);
                    }
        }
        __syncthreads();
    }

    // store merged fragments to xz[seqp][t][b][n] (element layout, float2)
    float* xz = (seq < 2) ? g_xzA : g_xzB;
    const long zb = ((long)(seq & 1) * TN_ + t) * BN_;
    #pragma unroll
    for (int mi = 0; mi < 2; mi++) {
        #pragma unroll
        for (int ni = 0; ni < 4; ni++) {
            float2 c01 = __half22float2(*(__half2*)&acch[mi][ni][0]);
            float2 c23 = __half22float2(*(__half2*)&acch[mi][ni][1]);
            int col = n0 + warp_n * 32 + ni * 8 + 2 * (lane & 3);
            int r0  = b0 + warp_m * 32 + mi * 16 + (lane >> 2);
            float2 v01 = make_float2(acc[mi][ni][0] + c01.x, acc[mi][ni][1] + c01.y);
            float2 v23 = make_float2(acc[mi][ni][2] + c23.x, acc[mi][ni][3] + c23.y);
            *(float2*)&xz[(zb + r0)     * FOURH + col] = v01;
            *(float2*)&xz[(zb + r0 + 8) * FOURH + col] = v23;
        }
    }
}

// ---------------------------------------------------------------------------
// Per-step LSTM: z = xz[t] + h @ Wh  (K=512, 8 chunks). 512 threads, 16 warps
// (4m x 4n), warp tile 32x32. acc initialized from precomputed xz.
#define ST_BYTES 65536
#define OFF_AL   16384
#define OFF_BH   32768
#define OFF_BL   49152
#define OFF_BIAS 131072
#define SMEM_TOTAL_STEP 131584

__global__ __launch_bounds__(512) void lstm_step_mma(const int* __restrict__ plen,
                                                     const int* __restrict__ hlen,
                                                     int s) {
    extern __shared__ char smem[];
    const uint32_t sbase = smem_u32(smem);
    const int tid  = threadIdx.x;
    const int lane = tid & 31;
    const int wid  = tid >> 5;
    const int warp_m = wid >> 2;       // 0..3
    const int warp_n = wid & 3;        // 0..3

    const int seq = blockIdx.z;
    const int rev = seq & 1;
    const int t   = rev ? (TN_ - 1 - s) : s;
    const int b0  = blockIdx.y * 128;
    const int n0  = blockIdx.x * 128;
    const int cur = s & 1;

    if (tid < 128)
        *(float*)(smem + OFF_BIAS + tid * 4) = g_bp[seq * FOURH + n0 + tid];

    const long hin_base  = ((long)cur * 4 + seq) * (BN_ * HN_);
    const long hout_base = ((long)(cur ^ 1) * 4 + seq) * (BN_ * HN_);

    auto load_chunk = [&](int k, int p) {
        const uint32_t st = sbase + (p ? ST_BYTES : 0);
        const int k0 = k * 64;
        #pragma unroll
        for (int j = 0; j < 2; j++) {           // A = h: hi + lo
            int idx = tid + 512 * j;
            int row = idx >> 3;
            int seg = idx & 7;
            long base = hin_base + (long)(b0 + row) * HN_ + k0 + seg * 8;
            uint32_t dst = st + ((row * 8 + (seg ^ (row & 7))) << 4);
            cp16(dst,          g_hhi + base);
            cp16(dst + OFF_AL, g_hlo + base);
        }
        #pragma unroll
        for (int j = 0; j < 2; j++) {           // B = Wh region: hi + lo
            int idx = tid + 512 * j;
            int row = idx >> 3;
            int seg = idx & 7;
            long base = ((long)seq * FOURH + n0 + row) * KPAD + XPAD + k0 + seg * 8;
            uint32_t dst = st + OFF_BH + ((row * 8 + (seg ^ (row & 7))) << 4);
            cp16(dst,         g_whi + base);
            cp16(dst + 16384, g_wlo + base);
        }
        CP_COMMIT();
    };

    // acc init from precomputed xz
    float acc[2][4][4];
    uint32_t acch[2][4][2];
    {
        const float* xz = (seq < 2) ? g_xzA : g_xzB;
        const long zb = ((long)(seq & 1) * TN_ + t) * BN_;
        #pragma unroll
        for (int mi = 0; mi < 2; mi++)
            #pragma unroll
            for (int ni = 0; ni < 4; ni++) {
                int col = n0 + warp_n * 32 + ni * 8 + 2 * (lane & 3);
                int r0  = b0 + warp_m * 32 + mi * 16 + (lane >> 2);
                float2 v01 = *(const float2*)&xz[(zb + r0)     * FOURH + col];
                float2 v23 = *(const float2*)&xz[(zb + r0 + 8) * FOURH + col];
                acc[mi][ni][0] = v01.x; acc[mi][ni][1] = v01.y;
                acc[mi][ni][2] = v23.x; acc[mi][ni][3] = v23.y;
                acch[mi][ni][0] = 0u; acch[mi][ni][1] = 0u;
            }
    }

    int arowb[2], arowx[2];
    #pragma unroll
    for (int mi = 0; mi < 2; mi++) {
        int r = warp_m * 32 + mi * 16 + (lane & 15);
        arowb[mi] = r * 128;
        arowx[mi] = r & 7;
    }
    int brow[2], browx[2];
    #pragma unroll
    for (int np = 0; np < 2; np++) {
        int n = warp_n * 32 + np * 16 + ((lane >> 4) << 3) + (lane & 7);
        brow[np]  = n * 128;
        browx[np] = n & 7;
    }
    const int asel = lane >> 4;
    const int bsel = (lane >> 3) & 1;

    load_chunk(0, 0);

    for (int k = 0; k < NCHS; k++) {
        const int p = k & 1;
        if (k + 1 < NCHS) load_chunk(k + 1, p ^ 1);
        if (k + 1 < NCHS) CP_WAIT(1); else CP_WAIT(0);
        __syncthreads();

        const uint32_t st = sbase + (p ? ST_BYTES : 0);
        #pragma unroll
        for (int kk = 0; kk < 4; kk++) {
            uint32_t ah[2][4], al[2][4];
            #pragma unroll
            for (int mi = 0; mi < 2; mi++) {
                int seg = 2 * kk + asel;
                uint32_t off = arowb[mi] + ((seg ^ arowx[mi]) << 4);
                LDSM_X4(ah[mi][0], ah[mi][1], ah[mi][2], ah[mi][3], st + off);
                LDSM_X4(al[mi][0], al[mi][1], al[mi][2], al[mi][3], st + OFF_AL + off);
            }
            uint32_t bh[2][4], bl[2][4];
            #pragma unroll
            for (int np = 0; np < 2; np++) {
                int seg = 2 * kk + bsel;
                uint32_t off = brow[np] + ((seg ^ browx[np]) << 4);
                LDSM_X4(bh[np][0], bh[np][1], bh[np][2], bh[np][3], st + OFF_BH + off);
                LDSM_X4(bl[np][0], bl[np][1], bl[np][2], bl[np][3], st + OFF_BL + off);
            }
            #pragma unroll
            for (int mi = 0; mi < 2; mi++)
                #pragma unroll
                for (int np = 0; np < 2; np++)
                    #pragma unroll
                    for (int h = 0; h < 2; h++) {
                        int ni = np * 2 + h;
                        uint32_t bhf[2] = { bh[np][2 * h], bh[np][2 * h + 1] };
                        uint32_t blf[2] = { bl[np][2 * h], bl[np][2 * h + 1] };
                        MMA16816 (acc[mi][ni],  ah[mi], bhf);
                        MMA16816H(acch[mi][ni], ah[mi], blf);
                        MMA16816H(acch[mi][ni], al[mi], bhf);
                    }
        }
        __syncthreads();
    }

    // ---- epilogue: merge corrections, gates + masked state update ---------
    const int* __restrict__ len = (seq < 2) ? plen : hlen;
    const float* bias_s = (const float*)(smem + OFF_BIAS);
    const bool amain = ((lane & 1) == 0);

    #pragma unroll
    for (int mi = 0; mi < 2; mi++) {
        #pragma unroll
        for (int ni = 0; ni < 4; ni++) {
            float2 c01 = __half22float2(*(__half2*)&acch[mi][ni][0]);
            float2 c23 = __half22float2(*(__half2*)&acch[mi][ni][1]);
            int col_local = warp_n * 32 + ni * 8 + 2 * (lane & 3);
            float v0 = acc[mi][ni][0] + c01.x + bias_s[col_local];
            float v1 = acc[mi][ni][1] + c01.y + bias_s[col_local + 1];
            float v2 = acc[mi][ni][2] + c23.x + bias_s[col_local];
            float v3 = acc[mi][ni][3] + c23.y + bias_s[col_local + 1];
            float p0 = __shfl_xor_sync(0xffffffffu, v0, 1);
            float p1 = __shfl_xor_sync(0xffffffffu, v1, 1);
            float p2 = __shfl_xor_sync(0xffffffffu, v2, 1);
            float p3 = __shfl_xor_sync(0xffffffffu, v3, 1);
            if (amain) {
                int u = (n0 + col_local) >> 2;
                #pragma unroll
                for (int rh = 0; rh < 2; rh++) {
                    int b = b0 + warp_m * 32 + mi * 16 + (lane >> 2) + rh * 8;
                    float iv = rh ? v2 : v0;
                    float jv = rh ? v3 : v1;
                    float fv = rh ? p2 : p0;
                    float ov = rh ? p3 : p1;
                    bool m = (t < len[b]);
                    long hidx = (long)b * HN_ + u;
                    float c_old = g_c[seq][b][u];
                    float nc = c_old * sigmoidf_(fv + 1.0f) + sigmoidf_(iv) * tanhf(jv);
                    float nh = tanhf(nc) * sigmoidf_(ov);
                    g_c[seq][b][u] = m ? nc : c_old;
                    __half hh, hl;
                    if (m) {
                        hh = __float2half(nh);
                        hl = __float2half(nh - __half2float(hh));
                    } else {
                        hh = g_hhi[hin_base + hidx];
                        hl = g_hlo[hin_base + hidx];
                    }
                    g_hhi[hout_base + hidx] = hh;
                    g_hlo[hout_base + hidx] = hl;
                }
            }
        }
    }
}

// ---------------------------------------------------------------------------
// MLP head (fp32)
__global__ void gather_x_kernel() {
    int i = blockIdx.x * blockDim.x + threadIdx.x;
    if (i >= BN_ * FOURH) return;
    int b   = i >> 11;
    int col = i & 2047;
    g_x[i] = g_c[col >> 9][b][col & 511];
}

#define BMT 64
#define BUT 64
#define KT  16
__global__ __launch_bounds__(256) void mlp_gemm_kernel(const float* __restrict__ W,
                                                       const float* __restrict__ bias,
                                                       int layer) {
    const float* A; float* C; int K, N;
    if (layer == 1)      { A = g_x;  C = g_m1; K = 2048; N = 1024; }
    else if (layer == 2) { A = g_m1; C = g_m2; K = 1024; N = 1024; }
    else                 { A = g_m2; C = g_m3; K = 1024; N = 1024; }

    const int m0 = blockIdx.y * BMT;
    const int n0 = blockIdx.x * BUT;
    __shared__ float As[KT][BMT];
    __shared__ float Bs[KT][BUT];
    const int tid = threadIdx.x;
    const int r0  = (tid >> 4) * 4;
    const int nt0 = (tid & 15) * 4;

    float acc[4][4];
    #pragma unroll
    for (int r = 0; r < 4; r++)
        #pragma unroll
        for (int u = 0; u < 4; u++) acc[r][u] = 0.0f;

    for (int k0 = 0; k0 < K; k0 += KT) {
        {
            int r  = tid >> 2;
            int kq = (tid & 3) * 4;
            #pragma unroll
            for (int i = 0; i < 4; i++)
                As[kq + i][r] = A[(m0 + r) * K + k0 + kq + i];
        }
        {
            int kk = tid >> 4;
            int uu = (tid & 15) * 4;
            *(float4*)&Bs[kk][uu] = *(const float4*)(W + (k0 + kk) * N + n0 + uu);
        }
        __syncthreads();
        #pragma unroll
        for (int kk = 0; kk < KT; kk++) {
            float4 a4 = *(const float4*)&As[kk][r0];
            float4 b4 = *(const float4*)&Bs[kk][nt0];
            float av[4] = {a4.x, a4.y, a4.z, a4.w};
            float bv[4] = {b4.x, b4.y, b4.z, b4.w};
            #pragma unroll
            for (int r = 0; r < 4; r++)
                #pragma unroll
                for (int u = 0; u < 4; u++)
                    acc[r][u] = fmaf(av[r], bv[u], acc[r][u]);
        }
        __syncthreads();
    }
    #pragma unroll
    for (int r = 0; r < 4; r++)
        #pragma unroll
        for (int u = 0; u < 4; u++) {
            int n = n0 + nt0 + u;
            C[(m0 + r0 + r) * N + n] = tanhf(acc[r][u] + bias[n]);
        }
}

__global__ void final_logits_kernel(const float* __restrict__ W4,
                                    const float* __restrict__ b4,
                                    float* __restrict__ out) {
    int b    = blockIdx.x;
    int w    = threadIdx.x >> 5;
    int lane = threadIdx.x & 31;
    if (w >= 3) return;
    float sum = 0.0f;
    for (int k = lane; k < 1024; k += 32)
        sum += g_m3[b * 1024 + k] * W4[k * 3 + w];
    #pragma unroll
    for (int off = 16; off; off >>= 1)
        sum += __shfl_down_sync(0xffffffff, sum, off);
    if (lane == 0) out[b * 3 + w] = sum + b4[w];
}

// ---------------------------------------------------------------------------
extern "C" void kernel_launch(void* const* d_in, const int* in_sizes, int n_in,
                              void* d_out, int out_size) {
    const float* premises   = (const float*)d_in[0];
    const float* hypotheses = (const float*)d_in[1];
    const int*   plen       = (const int*)d_in[2];
    const int*   hlen       = (const int*)d_in[3];

    WPtrs wp;
    for (int i = 0; i < 4; i++) {
        wp.wx[i]   = (const float*)d_in[4 + 3 * i + 0];
        wp.wh[i]   = (const float*)d_in[4 + 3 * i + 1];
        wp.bias[i] = (const float*)d_in[4 + 3 * i + 2];
    }
    const float* W1 = (const float*)d_in[16];
    const float* b1 = (const float*)d_in[17];
    const float* W2 = (const float*)d_in[18];
    const float* b2 = (const float*)d_in[19];
    const float* W3 = (const float*)d_in[20];
    const float* b3 = (const float*)d_in[21];
    const float* W4 = (const float*)d_in[22];
    const float* b4 = (const float*)d_in[23];
    float* out = (float*)d_out;

    cudaFuncSetAttribute(lstm_step_mma, cudaFuncAttributeMaxDynamicSharedMemorySize,
                         SMEM_TOTAL_STEP);
    cudaFuncSetAttribute(xz_gemm, cudaFuncAttributeMaxDynamicSharedMemorySize,
                         SMEM_XZ);

    // 1) preprocessing (one launch)
    {
        long long n = NTOT_;
        preproc_all<<<(unsigned)((n + 255) / 256), 256>>>(premises, hypotheses, wp);
    }

    // 2) xz = x @ Wx for all seqs/timesteps (one big parallel GEMM)
    xz_gemm<<<dim3(32, 2, 4 * TN_), 256, SMEM_XZ>>>();

    // 3) recurrence over h only (K=512)
    dim3 grid(16, 2, 4);
    for (int s = 0; s < TN_; s++)
        lstm_step_mma<<<grid, 512, SMEM_TOTAL_STEP>>>(plen, hlen, s);

    // 4) MLP head
    gather_x_kernel<<<(BN_ * FOURH + 255) / 256, 256>>>();
    mlp_gemm_kernel<<<dim3(1024 / BUT, BN_ / BMT), 256>>>(W1, b1, 1);
    mlp_gemm_kernel<<<dim3(1024 / BUT, BN_ / BMT), 256>>>(W2, b2, 2);
    mlp_gemm_kernel<<<dim3(1024 / BUT, BN_ / BMT), 256>>>(W3, b3, 3);
    final_logits_kernel<<<BN_, 96>>>(W4, b4, out);
}